// round 16
// baseline (speedup 1.0000x reference)
#include <cuda_runtime.h>
#include <cuda_fp16.h>
#include <math.h>

#define BB 128
#define NN 1024
#define DD 256
#define KS 8
#define HID 1024
#define EPSF 1e-6f
#define LN_EPS 1e-6f
#define SCALE_QK 0.0625f

// ---------------- device scratch ----------------
__device__ __half g_kvh[(size_t)BB * NN * 512]; // [token][0:256]=k fp16, [256:512]=v fp16
__device__ __half g_xh[(size_t)BB * NN * DD];   // LN'd tokens, fp16
__device__ __half g_wh[256 * 512];              // [Wk|Wv] fp16, k-major
__device__ float  g_slots[BB * KS * DD];
__device__ __half g_slotsh[BB * KS * DD];
__device__ __half g_slnh[BB * KS * DD];         // LN'd slots fp16
__device__ __half g_qh[BB * KS * DD];           // q fp16
__device__ float  g_masks[BB * KS * NN];        // softmax masks (output #2)
__device__ __half g_maskh[BB * KS * NN];        // (mask+eps) fp16 for updates GEMM
__device__ float  g_msum[BB * KS * 16];         // per-64tok-chunk mask sums
__device__ __half g_updatesh[BB * KS * DD];
__device__ float  g_gates[BB * KS * 1024];      // [rsum|zsum|inn|hn]
__device__ __half g_hiddenh[BB * KS * HID];
__device__ __half g_wgruh[512 * 1024];          // padded GRU weight fp16
__device__ float  g_bgru[1024];
__device__ __half g_whq[256 * 256];
__device__ __half g_wh1[256 * 1024];
__device__ __half g_wh2[1024 * 256];

// ---------------- helpers ----------------
__device__ __forceinline__ unsigned smem_u32(const void* p) {
    unsigned a;
    asm("{ .reg .u64 t; cvta.to.shared.u64 t, %1; cvt.u32.u64 %0, t; }" : "=r"(a) : "l"(p));
    return a;
}
__device__ __forceinline__ void ldsm_x4(unsigned* r, unsigned addr) {
    asm volatile("ldmatrix.sync.aligned.m8n8.x4.shared.b16 {%0,%1,%2,%3}, [%4];"
                 : "=r"(r[0]), "=r"(r[1]), "=r"(r[2]), "=r"(r[3]) : "r"(addr));
}
__device__ __forceinline__ void ldsm_x4_t(unsigned* r, unsigned addr) {
    asm volatile("ldmatrix.sync.aligned.m8n8.x4.trans.shared.b16 {%0,%1,%2,%3}, [%4];"
                 : "=r"(r[0]), "=r"(r[1]), "=r"(r[2]), "=r"(r[3]) : "r"(addr));
}
__device__ __forceinline__ void mma_f16(float* d, const unsigned* a, const unsigned* b) {
    asm volatile(
        "mma.sync.aligned.m16n8k16.row.col.f32.f16.f16.f32 "
        "{%0,%1,%2,%3}, {%4,%5,%6,%7}, {%8,%9}, {%0,%1,%2,%3};\n"
        : "+f"(d[0]), "+f"(d[1]), "+f"(d[2]), "+f"(d[3])
        : "r"(a[0]), "r"(a[1]), "r"(a[2]), "r"(a[3]), "r"(b[0]), "r"(b[1]));
}
__device__ __forceinline__ void cp_async16(unsigned dst, const void* src) {
    asm volatile("cp.async.cg.shared.global [%0], [%1], 16;" :: "r"(dst), "l"(src) : "memory");
}
#define CP_COMMIT() asm volatile("cp.async.commit_group;" ::: "memory")
#define CP_WAIT1()  asm volatile("cp.async.wait_group 1;" ::: "memory")
#define CP_WAIT0()  asm volatile("cp.async.wait_group 0;" ::: "memory")

// ---------------- merged prep: gru | wkv | whq | wh1 | wh2 | init_slots ----------------
__global__ void k_prep_all(const float* __restrict__ init_slots,
                           const float* __restrict__ Wk, const float* __restrict__ Wv,
                           const float* __restrict__ Wih, const float* __restrict__ Whh,
                           const float* __restrict__ bih, const float* __restrict__ bhh,
                           const float* __restrict__ Wq, const float* __restrict__ W1,
                           const float* __restrict__ W2) {
    int blk = blockIdx.x, t = threadIdx.x;
    if (blk < 2048) {                       // GRU prep over 512*1024
        int idx = blk * 256 + t;
        int k = idx >> 10, c = idx & 1023;
        int grp = c >> 8, cc = c & 255;
        float v = 0.f;
        if (k < 256) {
            if (grp < 3) v = Wih[k * 768 + grp * 256 + cc];
        } else {
            int kk = k - 256;
            if (grp < 2)       v = Whh[kk * 768 + grp * 256 + cc];
            else if (grp == 3) v = Whh[kk * 768 + 512 + cc];
        }
        g_wgruh[idx] = __float2half_rn(v);
        if (idx < 1024) {
            int g2 = idx >> 8, c2 = idx & 255;
            float bb;
            if (g2 < 2)       bb = bih[g2 * 256 + c2] + bhh[g2 * 256 + c2];
            else if (g2 == 2) bb = bih[512 + c2];
            else              bb = bhh[512 + c2];
            g_bgru[idx] = bb;
        }
    } else if (blk < 2560) {                // [Wk|Wv] pack over 256*512
        int idx = (blk - 2048) * 256 + t;
        int k = idx >> 9, c = idx & 511;
        float v = (c < 256) ? Wk[k * 256 + c] : Wv[k * 256 + (c - 256)];
        g_wh[idx] = __float2half_rn(v);
    } else if (blk < 2816) {                // Wq pack 256*256
        int idx = (blk - 2560) * 256 + t;
        g_whq[idx] = __float2half_rn(Wq[idx]);
    } else if (blk < 3840) {                // W1 pack 256*1024
        int idx = (blk - 2816) * 256 + t;
        g_wh1[idx] = __float2half_rn(W1[idx]);
    } else if (blk < 4864) {                // W2 pack 1024*256
        int idx = (blk - 3840) * 256 + t;
        g_wh2[idx] = __float2half_rn(W2[idx]);
    } else {                                // init slots 1024*... 4 blocks
        int idx = (blk - 4864) * 256 + t;   // 8 blocks cover 2048... need 262144/256=1024? no: BB*KS*DD=262144
        // handled below with loop
        for (int i = idx; i < BB * KS * DD; i += 8 * 256) {
            float v = init_slots[i];
            g_slots[i] = v;
            g_slotsh[i] = __float2half_rn(v);
        }
    }
}

// ---------------- token LN -> fp16 g_xh ----------------
__global__ __launch_bounds__(256) void k_ln_apply(const float* __restrict__ t,
                                                  const float* __restrict__ g,
                                                  const float* __restrict__ b) {
    int row  = blockIdx.x * 8 + (threadIdx.x >> 5);
    int lane = threadIdx.x & 31;
    const float* p = t + (size_t)row * DD;
    float vals[8]; float s = 0.f, s2 = 0.f;
#pragma unroll
    for (int i = 0; i < 8; i++) { float x = p[lane + i * 32]; vals[i] = x; s += x; s2 += x * x; }
#pragma unroll
    for (int o = 16; o; o >>= 1) {
        s  += __shfl_xor_sync(0xFFFFFFFFu, s,  o);
        s2 += __shfl_xor_sync(0xFFFFFFFFu, s2, o);
    }
    float mean = s * (1.f / DD);
    float inv  = rsqrtf(s2 * (1.f / DD) - mean * mean + LN_EPS);
#pragma unroll
    for (int i = 0; i < 8; i++) {
        int c = lane + i * 32;
        g_xh[(size_t)row * DD + c] = __float2half_rn((vals[i] - mean) * inv * g[c] + b[c]);
    }
}

// ================= fp16 KV GEMM v3: BN=64, 3-stage ring, single sync/stage =================
// grid (8, 1024), 256 threads (8 warps: 4 along M x 2 along N), warp tile 32x32.
__global__ __launch_bounds__(256) void k_gemm_kv_a(const float* __restrict__ bk,
                                                   const float* __restrict__ bv) {
    __shared__ __half sA[3][128 * 40];   // 10240 B/stage
    __shared__ __half sB[3][32 * 72];    //  4608 B/stage  (total 44.5 KB)

    int tid = threadIdx.x;
    int warp = tid >> 5, lane = tid & 31;
    int wm = warp & 3, wn = warp >> 2;
    int lr = lane >> 2, lc = lane & 3;
    int col0 = blockIdx.x * 64;
    int row0 = blockIdx.y * 128;
    const float* bias = (col0 < 256) ? bk : bv;
    int wcol0 = (col0 < 256) ? col0 : col0 - 256;

    unsigned baseA0 = smem_u32(&sA[0][0]);
    unsigned baseB0 = smem_u32(&sB[0][0]);

    auto load_stage = [&](int sidx, int bf) {
        int k0 = sidx * 32;
#pragma unroll
        for (int l = 0; l < 2; l++) {
            int task = tid + l * 256;          // 0..511  (128 rows x 4 chunks)
            int r = task >> 2, ch = task & 3;
            cp_async16(baseA0 + (unsigned)(bf * 128 * 40 + r * 40 + ch * 8) * 2,
                       g_xh + (size_t)(row0 + r) * DD + k0 + ch * 8);
        }
        {
            int r = tid >> 3, ch = tid & 7;    // 32 rows x 8 chunks
            cp_async16(baseB0 + (unsigned)(bf * 32 * 72 + r * 72 + ch * 8) * 2,
                       g_wh + (size_t)(k0 + r) * 512 + col0 + ch * 8);
        }
        CP_COMMIT();
    };

    load_stage(0, 0);
    load_stage(1, 1);

    float acc[2][4][4];
#pragma unroll
    for (int mt = 0; mt < 2; mt++)
#pragma unroll
        for (int nt = 0; nt < 4; nt++)
#pragma unroll
            for (int i = 0; i < 4; i++) acc[mt][nt][i] = 0.f;

    for (int s = 0; s < 8; s++) {
        if (s + 1 < 8) CP_WAIT1(); else CP_WAIT0();
        __syncthreads();
        int bf = s % 3;
        unsigned baseA = baseA0 + (unsigned)(bf * 128 * 40) * 2;
        unsigned baseB = baseB0 + (unsigned)(bf * 32 * 72) * 2;
#pragma unroll
        for (int ks = 0; ks < 2; ks++) {
            int kb = ks * 16;
            unsigned a[2][4], b[2][4];
#pragma unroll
            for (int mt = 0; mt < 2; mt++) {
                int r = wm * 32 + mt * 16 + (lane & 15);
                ldsm_x4(a[mt], baseA + (unsigned)(r * 40 + kb + (lane >> 4) * 8) * 2);
            }
#pragma unroll
            for (int p = 0; p < 2; p++) {
                int kr = kb + (lane & 7) + ((lane >> 3) & 1) * 8;
                int cn = wn * 32 + p * 16 + (lane >> 4) * 8;
                ldsm_x4_t(b[p], baseB + (unsigned)(kr * 72 + cn) * 2);
            }
#pragma unroll
            for (int mt = 0; mt < 2; mt++)
#pragma unroll
                for (int p = 0; p < 2; p++) {
                    mma_f16(acc[mt][2 * p],     a[mt], &b[p][0]);
                    mma_f16(acc[mt][2 * p + 1], a[mt], &b[p][2]);
                }
        }
        if (s + 2 < 8) load_stage(s + 2, (s + 2) % 3);
    }

#pragma unroll
    for (int mt = 0; mt < 2; mt++)
#pragma unroll
        for (int nt = 0; nt < 4; nt++) {
            int r  = row0 + wm * 32 + mt * 16 + lr;
            int cl = wn * 32 + nt * 8 + lc * 2;
            int wc = wcol0 + cl;
            float b0 = bias[wc], b1 = bias[wc + 1];
            size_t o0 = (size_t)r * 512 + col0 + cl;
            size_t o1 = (size_t)(r + 8) * 512 + col0 + cl;
            *(__half2*)(g_kvh + o0) = __floats2half2_rn(acc[mt][nt][0] + b0, acc[mt][nt][1] + b1);
            *(__half2*)(g_kvh + o1) = __floats2half2_rn(acc[mt][nt][2] + b0, acc[mt][nt][3] + b1);
        }
}

// ================= unified small fp16 GEMM (3-stage ring) =================
// MODE 1: qprj g_slnh@g_whq+bq -> g_qh fp16
// MODE 2: gru  [g_updatesh|g_slotsh]@g_wgruh+g_bgru -> g_gates fp32
// MODE 3: mlp1 gelu(g_slnh@g_wh1+b1) -> g_hiddenh fp16
// MODE 4: mlp2 g_slots += g_hiddenh@g_wh2+b2 -> g_slots fp32 + g_slotsh fp16
template<int MODE>
__global__ __launch_bounds__(128) void hgemm(const float* __restrict__ bias_in) {
    constexpr int N   = (MODE == 2 || MODE == 3) ? 1024 : 256;
    constexpr int K   = (MODE == 2) ? 512 : (MODE == 4) ? 1024 : 256;
    constexpr int LDB = (MODE == 2 || MODE == 3) ? 1024 : 256;
    constexpr int LDA = (MODE == 4) ? 1024 : 256;
    constexpr int NSTAGE = K / 32;

    __shared__ __half sA[3][64 * 40];
    __shared__ __half sB[3][32 * 72];

    const __half* Abase = (MODE == 2) ? g_updatesh : (MODE == 4) ? g_hiddenh : g_slnh;
    const __half* Bh    = (MODE == 1) ? g_whq : (MODE == 2) ? g_wgruh
                        : (MODE == 3) ? g_wh1 : g_wh2;
    const float* biasp  = (MODE == 2) ? g_bgru : bias_in;

    int tid = threadIdx.x;
    int warp = tid >> 5, lane = tid & 31;
    int wm = warp & 1, wn = warp >> 1;
    int lr = lane >> 2, lc = lane & 3;
    int row0 = blockIdx.y * 64;
    int col0 = blockIdx.x * 64;

    unsigned baseA0 = smem_u32(&sA[0][0]);
    unsigned baseB0 = smem_u32(&sB[0][0]);

    auto load_stage = [&](int sidx, int bf) {
        int k0 = sidx * 32;
        const __half* Ah = Abase; int koff = k0;
        if (MODE == 2 && k0 >= 256) { Ah = g_slotsh; koff = k0 - 256; }
#pragma unroll
        for (int l = 0; l < 2; l++) {
            int task = tid + l * 128;
            int r = task >> 2, ch = task & 3;
            cp_async16(baseA0 + (unsigned)(bf * 64 * 40 + r * 40 + ch * 8) * 2,
                       Ah + (size_t)(row0 + r) * LDA + koff + ch * 8);
        }
#pragma unroll
        for (int l = 0; l < 2; l++) {
            int task = tid + l * 128;
            int r = task >> 3, ch = task & 7;
            cp_async16(baseB0 + (unsigned)(bf * 32 * 72 + r * 72 + ch * 8) * 2,
                       Bh + (size_t)(k0 + r) * LDB + col0 + ch * 8);
        }
        CP_COMMIT();
    };

    load_stage(0, 0);
    load_stage(1, 1);

    float acc[2][4][4];
#pragma unroll
    for (int mt = 0; mt < 2; mt++)
#pragma unroll
        for (int nt = 0; nt < 4; nt++)
#pragma unroll
            for (int i = 0; i < 4; i++) acc[mt][nt][i] = 0.f;

    for (int s = 0; s < NSTAGE; s++) {
        if (s + 1 < NSTAGE) CP_WAIT1(); else CP_WAIT0();
        __syncthreads();
        int bf = s % 3;
        unsigned baseA = baseA0 + (unsigned)(bf * 64 * 40) * 2;
        unsigned baseB = baseB0 + (unsigned)(bf * 32 * 72) * 2;
#pragma unroll
        for (int ks = 0; ks < 2; ks++) {
            int kb = ks * 16;
            unsigned a[2][4], b[2][4];
#pragma unroll
            for (int mt = 0; mt < 2; mt++) {
                int r = wm * 32 + mt * 16 + (lane & 15);
                ldsm_x4(a[mt], baseA + (unsigned)(r * 40 + kb + (lane >> 4) * 8) * 2);
            }
#pragma unroll
            for (int p = 0; p < 2; p++) {
                int kr = kb + (lane & 7) + ((lane >> 3) & 1) * 8;
                int cn = wn * 32 + p * 16 + (lane >> 4) * 8;
                ldsm_x4_t(b[p], baseB + (unsigned)(kr * 72 + cn) * 2);
            }
#pragma unroll
            for (int mt = 0; mt < 2; mt++)
#pragma unroll
                for (int p = 0; p < 2; p++) {
                    mma_f16(acc[mt][2 * p],     a[mt], &b[p][0]);
                    mma_f16(acc[mt][2 * p + 1], a[mt], &b[p][2]);
                }
        }
        if (s + 2 < NSTAGE) load_stage(s + 2, (s + 2) % 3);
    }

#pragma unroll
    for (int mt = 0; mt < 2; mt++)
#pragma unroll
        for (int nt = 0; nt < 4; nt++) {
            int r = row0 + wm * 32 + mt * 16 + lr;
            int c = col0 + wn * 32 + nt * 8 + lc * 2;
            float b0 = biasp[c], b1 = biasp[c + 1];
            float v0 = acc[mt][nt][0] + b0, v1 = acc[mt][nt][1] + b1;
            float v2 = acc[mt][nt][2] + b0, v3 = acc[mt][nt][3] + b1;
            if (MODE == 3) {
                v0 = 0.5f * v0 * (1.f + erff(v0 * 0.70710678118654752f));
                v1 = 0.5f * v1 * (1.f + erff(v1 * 0.70710678118654752f));
                v2 = 0.5f * v2 * (1.f + erff(v2 * 0.70710678118654752f));
                v3 = 0.5f * v3 * (1.f + erff(v3 * 0.70710678118654752f));
                *(__half2*)(g_hiddenh + (size_t)r * N + c)       = __floats2half2_rn(v0, v1);
                *(__half2*)(g_hiddenh + (size_t)(r + 8) * N + c) = __floats2half2_rn(v2, v3);
            } else if (MODE == 4) {
                v0 += g_slots[(size_t)r * N + c];       v1 += g_slots[(size_t)r * N + c + 1];
                v2 += g_slots[(size_t)(r + 8) * N + c]; v3 += g_slots[(size_t)(r + 8) * N + c + 1];
                g_slots[(size_t)r * N + c] = v0;        g_slots[(size_t)r * N + c + 1] = v1;
                g_slots[(size_t)(r + 8) * N + c] = v2;  g_slots[(size_t)(r + 8) * N + c + 1] = v3;
                *(__half2*)(g_slotsh + (size_t)r * N + c)       = __floats2half2_rn(v0, v1);
                *(__half2*)(g_slotsh + (size_t)(r + 8) * N + c) = __floats2half2_rn(v2, v3);
            } else if (MODE == 1) {
                *(__half2*)(g_qh + (size_t)r * N + c)       = __floats2half2_rn(v0, v1);
                *(__half2*)(g_qh + (size_t)(r + 8) * N + c) = __floats2half2_rn(v2, v3);
            } else {
                g_gates[(size_t)r * N + c] = v0;       g_gates[(size_t)r * N + c + 1] = v1;
                g_gates[(size_t)(r + 8) * N + c] = v2; g_gates[(size_t)(r + 8) * N + c + 1] = v3;
            }
        }
}

// ================= logits via mma + softmax =================
__global__ __launch_bounds__(128) void k_logits_mma() {
    __shared__ __half sQ[16 * 264];
    __shared__ __half sK[64 * 264];
    __shared__ float  sC[16 * 72];
    int b  = blockIdx.y;
    int n0 = blockIdx.x * 64;
    int tid = threadIdx.x;
    int warp = tid >> 5, lane = tid & 31;

    unsigned qb = smem_u32(sQ);
    unsigned kb_ = smem_u32(sK);

#pragma unroll
    for (int l = 0; l < 4; l++) {
        int task = tid + l * 128;
        int row = task >> 5, seg = task & 31;
        uint4 v = make_uint4(0, 0, 0, 0);
        if (row < 8) v = *(const uint4*)(g_qh + (size_t)(b * KS + row) * DD + seg * 8);
        *(uint4*)&sQ[row * 264 + seg * 8] = v;
    }
#pragma unroll
    for (int l = 0; l < 16; l++) {
        int task = tid + l * 128;
        int row = task >> 5, seg = task & 31;
        cp_async16(kb_ + (unsigned)(row * 264 + seg * 8) * 2,
                   g_kvh + (size_t)(b * NN + n0 + row) * 512 + seg * 8);
    }
    CP_COMMIT(); CP_WAIT0();
    __syncthreads();

    unsigned aw[16][4];
#pragma unroll
    for (int ks = 0; ks < 16; ks++)
        ldsm_x4(aw[ks], qb + (unsigned)((lane & 15) * 264 + ks * 16 + (lane >> 4) * 8) * 2);

    float acc[2][4];
#pragma unroll
    for (int f = 0; f < 2; f++)
#pragma unroll
        for (int i = 0; i < 4; i++) acc[f][i] = 0.f;

    int tokw = warp * 16;
#pragma unroll
    for (int ks = 0; ks < 16; ks++) {
        unsigned r[4];
        int nl = tokw + (lane & 7) + ((lane >> 4) & 1) * 8;
        int kh = ((lane >> 3) & 1) * 8;
        ldsm_x4(r, kb_ + (unsigned)(nl * 264 + ks * 16 + kh) * 2);
        mma_f16(acc[0], aw[ks], &r[0]);
        mma_f16(acc[1], aw[ks], &r[2]);
    }

    int lr = lane >> 2, lc = lane & 3;
#pragma unroll
    for (int f = 0; f < 2; f++) {
        int col = tokw + f * 8 + lc * 2;
        sC[lr * 72 + col]           = acc[f][0];
        sC[lr * 72 + col + 1]       = acc[f][1];
        sC[(lr + 8) * 72 + col]     = acc[f][2];
        sC[(lr + 8) * 72 + col + 1] = acc[f][3];
    }
    __syncthreads();

    if (tid < 64) {
        int tok = tid;
        float lg[8];
        float m = -1e30f;
#pragma unroll
        for (int s = 0; s < 8; s++) { lg[s] = sC[s * 72 + tok] * SCALE_QK; m = fmaxf(m, lg[s]); }
        float sum = 0.f;
#pragma unroll
        for (int s = 0; s < 8; s++) { lg[s] = expf(lg[s] - m); sum += lg[s]; }
        float inv = 1.f / sum;
#pragma unroll
        for (int s = 0; s < 8; s++) {
            float mask = lg[s] * inv;
            g_masks[((size_t)b * KS + s) * NN + n0 + tok] = mask;
            g_maskh[((size_t)b * KS + s) * NN + n0 + tok] = __float2half_rn(mask + EPSF);
            sC[s * 72 + tok] = mask;
        }
    }
    __syncthreads();
    if (tid < 8) {
        float tot = 0.f;
#pragma unroll
        for (int j = 0; j < 64; j++) tot += sC[tid * 72 + j];
        g_msum[((size_t)b * KS + tid) * 16 + blockIdx.x] = tot;
    }
}

// ================= updates via mma, N-split x2 =================
__global__ __launch_bounds__(128) void k_updates_mma() {
    __shared__ __half sAt[2][16 * 72];
    __shared__ __half sV[2][32 * 136];
    __shared__ float sden[8];
    int b = blockIdx.x;
    int colbase = blockIdx.y * 128;
    int tid = threadIdx.x;
    int warp = tid >> 5, lane = tid & 31;

    unsigned ab = smem_u32(&sAt[0][0]);
    unsigned vb = smem_u32(&sV[0][0]);

    if (tid < 8) {
        float tot = 0.f;
#pragma unroll
        for (int c = 0; c < 16; c++) tot += g_msum[((size_t)b * KS + tid) * 16 + c];
        sden[tid] = 1.f / (tot + (float)NN * EPSF + EPSF);
    }

    auto load_A = [&](int ch, int bf) {
        if (tid < 64) {
            int row = tid >> 2, seg = tid & 3;
            uint4 v = make_uint4(0, 0, 0, 0);
            if (row < 8)
                v = *(const uint4*)(g_maskh + (size_t)(b * KS + row) * NN + ch * 32 + seg * 8);
            *(uint4*)&sAt[bf][row * 72 + seg * 8] = v;
        }
    };
    auto load_V = [&](int ch, int bf) {
#pragma unroll
        for (int l = 0; l < 4; l++) {
            int task = tid + l * 128;
            int row = task >> 4, seg = task & 15;
            cp_async16(vb + (unsigned)(bf * 32 * 136 + row * 136 + seg * 8) * 2,
                       g_kvh + (size_t)(b * NN + ch * 32 + row) * 512 + 256 + colbase + seg * 8);
        }
        CP_COMMIT();
    };

    load_A(0, 0);
    load_V(0, 0);

    float acc[4][4];
#pragma unroll
    for (int g = 0; g < 4; g++)
#pragma unroll
        for (int i = 0; i < 4; i++) acc[g][i] = 0.f;

    for (int ch = 0; ch < 32; ch++) {
        if (ch < 31) { load_A(ch + 1, (ch + 1) & 1); load_V(ch + 1, (ch + 1) & 1); CP_WAIT1(); }
        else         { CP_WAIT0(); }
        __syncthreads();
        int bf = ch & 1;
        unsigned aB = ab + (unsigned)(bf * 16 * 72) * 2;
        unsigned vB = vb + (unsigned)(bf * 32 * 136) * 2;
#pragma unroll
        for (int ks = 0; ks < 2; ks++) {
            int kb = ks * 16;
            unsigned a[4];
            ldsm_x4(a, aB + (unsigned)((lane & 15) * 72 + kb + (lane >> 4) * 8) * 2);
#pragma unroll
            for (int g2 = 0; g2 < 2; g2++) {
                unsigned bfrag[4];
                int kr = kb + (lane & 7) + ((lane >> 3) & 1) * 8;
                int cn = warp * 32 + g2 * 16 + (lane >> 4) * 8;
                ldsm_x4_t(bfrag, vB + (unsigned)(kr * 136 + cn) * 2);
                mma_f16(acc[g2 * 2],     a, &bfrag[0]);
                mma_f16(acc[g2 * 2 + 1], a, &bfrag[2]);
            }
        }
        __syncthreads();
    }

    int lr = lane >> 2, lc = lane & 3;
    float inv = sden[lr];
#pragma unroll
    for (int g = 0; g < 4; g++) {
        int col = colbase + warp * 32 + (g >> 1) * 16 + (g & 1) * 8 + lc * 2;
        *(__half2*)(g_updatesh + (size_t)(b * KS + lr) * DD + col) =
            __floats2half2_rn(acc[g][0] * inv, acc[g][1] * inv);
    }
}

// ---------------- LN of slots -> g_slnh ----------------
__global__ __launch_bounds__(256) void k_ln_slots(const float* __restrict__ g,
                                                  const float* __restrict__ b) {
    int row = blockIdx.x, c = threadIdx.x;
    float x = g_slots[row * DD + c];
    float s1 = x, s2 = x * x;
#pragma unroll
    for (int o = 16; o; o >>= 1) {
        s1 += __shfl_xor_sync(0xFFFFFFFFu, s1, o);
        s2 += __shfl_xor_sync(0xFFFFFFFFu, s2, o);
    }
    __shared__ float r1[8], r2[8];
    if ((c & 31) == 0) { r1[c >> 5] = s1; r2[c >> 5] = s2; }
    __syncthreads();
    float t1 = 0.f, t2 = 0.f;
#pragma unroll
    for (int w = 0; w < 8; w++) { t1 += r1[w]; t2 += r2[w]; }
    float mean = t1 * (1.f / DD);
    float inv  = rsqrtf(t2 * (1.f / DD) - mean * mean + LN_EPS);
    g_slnh[row * DD + c] = __float2half_rn((x - mean) * inv * g[c] + b[c]);
}

// ---------------- GRU gating + LN(slots) for MLP ----------------
__global__ __launch_bounds__(256) void k_gru_combine_ln(const float* __restrict__ lg,
                                                        const float* __restrict__ lb) {
    int row = blockIdx.x, c = threadIdx.x;
    const float* gt = g_gates + (size_t)row * 1024;
    float sp = g_slots[row * DD + c];
    float r = 1.f / (1.f + expf(-gt[c]));
    float z = 1.f / (1.f + expf(-gt[256 + c]));
    float n = tanhf(gt[512 + c] + r * gt[768 + c]);
    float sN = (1.f - z) * n + z * sp;
    g_slots[row * DD + c] = sN;
    float s1 = sN, s2 = sN * sN;
#pragma unroll
    for (int o = 16; o; o >>= 1) {
        s1 += __shfl_xor_sync(0xFFFFFFFFu, s1, o);
        s2 += __shfl_xor_sync(0xFFFFFFFFu, s2, o);
    }
    __shared__ float r1[8], r2[8];
    if ((c & 31) == 0) { r1[c >> 5] = s1; r2[c >> 5] = s2; }
    __syncthreads();
    float t1 = 0.f, t2 = 0.f;
#pragma unroll
    for (int w = 0; w < 8; w++) { t1 += r1[w]; t2 += r2[w]; }
    float mean = t1 * (1.f / DD);
    float inv  = rsqrtf(t2 * (1.f / DD) - mean * mean + LN_EPS);
    g_slnh[row * DD + c] = __float2half_rn((sN - mean) * inv * lg[c] + lb[c]);
}

// ---------------- pack output ----------------
__global__ void k_out(float* __restrict__ out, int total) {
    for (int idx = blockIdx.x * blockDim.x + threadIdx.x; idx < total;
         idx += gridDim.x * blockDim.x) {
        out[idx] = (idx < BB * KS * DD) ? g_slots[idx] : g_masks[idx - BB * KS * DD];
    }
}

// ---------------- launch ----------------
extern "C" void kernel_launch(void* const* d_in, const int* in_sizes, int n_in,
                              void* d_out, int out_size) {
    const float* tokens     = (const float*)d_in[0];
    const float* init_slots = (const float*)d_in[1];
    const float* ln_in_g    = (const float*)d_in[2];
    const float* ln_in_b    = (const float*)d_in[3];
    const float* Wk         = (const float*)d_in[4];
    const float* bk         = (const float*)d_in[5];
    const float* Wv         = (const float*)d_in[6];
    const float* bv         = (const float*)d_in[7];
    const float* ln_s_g     = (const float*)d_in[8];
    const float* ln_s_b     = (const float*)d_in[9];
    const float* Wq         = (const float*)d_in[10];
    const float* bq         = (const float*)d_in[11];
    const float* W_ih       = (const float*)d_in[12];
    const float* b_ih       = (const float*)d_in[13];
    const float* W_hh       = (const float*)d_in[14];
    const float* b_hh       = (const float*)d_in[15];
    const float* ln_m_g     = (const float*)d_in[16];
    const float* ln_m_b     = (const float*)d_in[17];
    const float* W1         = (const float*)d_in[18];
    const float* b1         = (const float*)d_in[19];
    const float* W2         = (const float*)d_in[20];
    const float* b2         = (const float*)d_in[21];

    k_prep_all<<<4872, 256>>>(init_slots, Wk, Wv, W_ih, W_hh, b_ih, b_hh, Wq, W1, W2);
    k_ln_apply<<<BB * NN / 8, 256>>>(tokens, ln_in_g, ln_in_b);
    k_gemm_kv_a<<<dim3(8, 1024), 256>>>(bk, bv);

    for (int it = 0; it < 3; it++) {
        k_ln_slots<<<BB * KS, 256>>>(ln_s_g, ln_s_b);
        hgemm<1><<<dim3(4, 16), 128>>>(bq);
        k_logits_mma<<<dim3(16, BB), 128>>>();
        k_updates_mma<<<dim3(BB, 2), 128>>>();
        hgemm<2><<<dim3(16, 16), 128>>>(nullptr);
        k_gru_combine_ln<<<BB * KS, 256>>>(ln_m_g, ln_m_b);
        hgemm<3><<<dim3(16, 16), 128>>>(b1);
        hgemm<4><<<dim3(4, 16), 128>>>(b2);
    }

    k_out<<<2560, 256>>>((float*)d_out, out_size);
}

// round 17
// speedup vs baseline: 1.0461x; 1.0461x over previous
#include <cuda_runtime.h>
#include <cuda_fp16.h>
#include <math.h>

#define BB 128
#define NN 1024
#define DD 256
#define KS 8
#define HID 1024
#define EPSF 1e-6f
#define LN_EPS 1e-6f
#define SCALE_QK 0.0625f

// ---------------- device scratch ----------------
__device__ __half g_kvh[(size_t)BB * NN * 512]; // [token][0:256]=k fp16, [256:512]=v fp16
__device__ __half g_xh[(size_t)BB * NN * DD];   // LN'd tokens, fp16
__device__ __half g_wh[256 * 512];              // [Wk|Wv] fp16, k-major
__device__ float  g_slots[BB * KS * DD];
__device__ __half g_slotsh[BB * KS * DD];
__device__ __half g_slnh[BB * KS * DD];         // LN'd slots fp16
__device__ __half g_qh[BB * KS * DD];           // q fp16
__device__ float  g_masks[BB * KS * NN];        // softmax masks (output #2)
__device__ __half g_maskh[BB * KS * NN];        // (mask+eps) fp16 for updates GEMM
__device__ float  g_msum[BB * KS * 16];         // per-64tok-chunk mask sums
__device__ __half g_updatesh[BB * KS * DD];
__device__ float  g_gates[BB * KS * 1024];      // [rsum|zsum|inn|hn]
__device__ __half g_hiddenh[BB * KS * HID];
__device__ __half g_wgruh[512 * 1024];          // padded GRU weight fp16
__device__ float  g_bgru[1024];
__device__ __half g_whq[256 * 256];
__device__ __half g_wh1[256 * 1024];
__device__ __half g_wh2[1024 * 256];

// ---------------- helpers ----------------
__device__ __forceinline__ unsigned smem_u32(const void* p) {
    unsigned a;
    asm("{ .reg .u64 t; cvta.to.shared.u64 t, %1; cvt.u32.u64 %0, t; }" : "=r"(a) : "l"(p));
    return a;
}
__device__ __forceinline__ void ldsm_x4(unsigned* r, unsigned addr) {
    asm volatile("ldmatrix.sync.aligned.m8n8.x4.shared.b16 {%0,%1,%2,%3}, [%4];"
                 : "=r"(r[0]), "=r"(r[1]), "=r"(r[2]), "=r"(r[3]) : "r"(addr));
}
__device__ __forceinline__ void ldsm_x4_t(unsigned* r, unsigned addr) {
    asm volatile("ldmatrix.sync.aligned.m8n8.x4.trans.shared.b16 {%0,%1,%2,%3}, [%4];"
                 : "=r"(r[0]), "=r"(r[1]), "=r"(r[2]), "=r"(r[3]) : "r"(addr));
}
__device__ __forceinline__ void mma_f16(float* d, const unsigned* a, const unsigned* b) {
    asm volatile(
        "mma.sync.aligned.m16n8k16.row.col.f32.f16.f16.f32 "
        "{%0,%1,%2,%3}, {%4,%5,%6,%7}, {%8,%9}, {%0,%1,%2,%3};\n"
        : "+f"(d[0]), "+f"(d[1]), "+f"(d[2]), "+f"(d[3])
        : "r"(a[0]), "r"(a[1]), "r"(a[2]), "r"(a[3]), "r"(b[0]), "r"(b[1]));
}
__device__ __forceinline__ void cp_async16(unsigned dst, const void* src) {
    asm volatile("cp.async.cg.shared.global [%0], [%1], 16;" :: "r"(dst), "l"(src) : "memory");
}
#define CP_COMMIT() asm volatile("cp.async.commit_group;" ::: "memory")
#define CP_WAIT1()  asm volatile("cp.async.wait_group 1;" ::: "memory")
#define CP_WAIT0()  asm volatile("cp.async.wait_group 0;" ::: "memory")

// ---------------- merged prep: gru | wkv | whq | wh1 | wh2 | init_slots ----------------
__global__ void k_prep_all(const float* __restrict__ init_slots,
                           const float* __restrict__ Wk, const float* __restrict__ Wv,
                           const float* __restrict__ Wih, const float* __restrict__ Whh,
                           const float* __restrict__ bih, const float* __restrict__ bhh,
                           const float* __restrict__ Wq, const float* __restrict__ W1,
                           const float* __restrict__ W2) {
    int blk = blockIdx.x, t = threadIdx.x;
    if (blk < 2048) {                       // GRU prep over 512*1024
        int idx = blk * 256 + t;
        int k = idx >> 10, c = idx & 1023;
        int grp = c >> 8, cc = c & 255;
        float v = 0.f;
        if (k < 256) {
            if (grp < 3) v = Wih[k * 768 + grp * 256 + cc];
        } else {
            int kk = k - 256;
            if (grp < 2)       v = Whh[kk * 768 + grp * 256 + cc];
            else if (grp == 3) v = Whh[kk * 768 + 512 + cc];
        }
        g_wgruh[idx] = __float2half_rn(v);
        if (idx < 1024) {
            int g2 = idx >> 8, c2 = idx & 255;
            float bb;
            if (g2 < 2)       bb = bih[g2 * 256 + c2] + bhh[g2 * 256 + c2];
            else if (g2 == 2) bb = bih[512 + c2];
            else              bb = bhh[512 + c2];
            g_bgru[idx] = bb;
        }
    } else if (blk < 2560) {                // [Wk|Wv] pack over 256*512
        int idx = (blk - 2048) * 256 + t;
        int k = idx >> 9, c = idx & 511;
        float v = (c < 256) ? Wk[k * 256 + c] : Wv[k * 256 + (c - 256)];
        g_wh[idx] = __float2half_rn(v);
    } else if (blk < 2816) {                // Wq pack 256*256
        int idx = (blk - 2560) * 256 + t;
        g_whq[idx] = __float2half_rn(Wq[idx]);
    } else if (blk < 3840) {                // W1 pack 256*1024
        int idx = (blk - 2816) * 256 + t;
        g_wh1[idx] = __float2half_rn(W1[idx]);
    } else if (blk < 4864) {                // W2 pack 1024*256
        int idx = (blk - 3840) * 256 + t;
        g_wh2[idx] = __float2half_rn(W2[idx]);
    } else {                                // init slots (8 blocks, grid-stride)
        int idx = (blk - 4864) * 256 + t;
        for (int i = idx; i < BB * KS * DD; i += 8 * 256) {
            float v = init_slots[i];
            g_slots[i] = v;
            g_slotsh[i] = __float2half_rn(v);
        }
    }
}

// ---------------- token LN -> fp16 g_xh ----------------
__global__ __launch_bounds__(256) void k_ln_apply(const float* __restrict__ t,
                                                  const float* __restrict__ g,
                                                  const float* __restrict__ b) {
    int row  = blockIdx.x * 8 + (threadIdx.x >> 5);
    int lane = threadIdx.x & 31;
    const float* p = t + (size_t)row * DD;
    float vals[8]; float s = 0.f, s2 = 0.f;
#pragma unroll
    for (int i = 0; i < 8; i++) { float x = p[lane + i * 32]; vals[i] = x; s += x; s2 += x * x; }
#pragma unroll
    for (int o = 16; o; o >>= 1) {
        s  += __shfl_xor_sync(0xFFFFFFFFu, s,  o);
        s2 += __shfl_xor_sync(0xFFFFFFFFu, s2, o);
    }
    float mean = s * (1.f / DD);
    float inv  = rsqrtf(s2 * (1.f / DD) - mean * mean + LN_EPS);
#pragma unroll
    for (int i = 0; i < 8; i++) {
        int c = lane + i * 32;
        g_xh[(size_t)row * DD + c] = __float2half_rn((vals[i] - mean) * inv * g[c] + b[c]);
    }
}

// ================= fp16 KV GEMM (cp.async, 2-stage, 64x32 warp tile — proven) =================
__global__ __launch_bounds__(256, 2) void k_gemm_kv_a(const float* __restrict__ bk,
                                                      const float* __restrict__ bv) {
    __shared__ __half sA[2][128 * 40];
    __shared__ __half sB[2][32 * 136];

    int tid = threadIdx.x;
    int warp = tid >> 5, lane = tid & 31;
    int wm = warp & 1, wn = warp >> 1;
    int lr = lane >> 2, lc = lane & 3;
    int col0 = blockIdx.x * 128;
    int row0 = blockIdx.y * 128;
    const float* bias = (col0 < 256) ? bk : bv;
    int wcol0 = (col0 < 256) ? col0 : col0 - 256;

    unsigned baseA0 = smem_u32(&sA[0][0]);
    unsigned baseB0 = smem_u32(&sB[0][0]);

    auto load_stage = [&](int k0, int bf) {
#pragma unroll
        for (int l = 0; l < 2; l++) {
            int task = tid + l * 256;
            int r = task >> 2, ch = task & 3;
            const __half* src = g_xh + (size_t)(row0 + r) * DD + k0 + ch * 8;
            cp_async16(baseA0 + (unsigned)(bf * 128 * 40 + r * 40 + ch * 8) * 2, src);
        }
#pragma unroll
        for (int l = 0; l < 2; l++) {
            int task = tid + l * 256;
            int r = task >> 4, ch = task & 15;
            const __half* src = g_wh + (size_t)(k0 + r) * 512 + col0 + ch * 8;
            cp_async16(baseB0 + (unsigned)(bf * 32 * 136 + r * 136 + ch * 8) * 2, src);
        }
        CP_COMMIT();
    };

    load_stage(0, 0);

    float acc[4][4][4];
#pragma unroll
    for (int mt = 0; mt < 4; mt++)
#pragma unroll
        for (int nt = 0; nt < 4; nt++)
#pragma unroll
            for (int i = 0; i < 4; i++) acc[mt][nt][i] = 0.f;

    for (int s = 0; s < 8; s++) {
        if (s < 7) { load_stage((s + 1) * 32, (s + 1) & 1); CP_WAIT1(); }
        else       { CP_WAIT0(); }
        __syncthreads();
        int bf = s & 1;
        unsigned baseA = baseA0 + (unsigned)(bf * 128 * 40) * 2;
        unsigned baseB = baseB0 + (unsigned)(bf * 32 * 136) * 2;
#pragma unroll
        for (int ks = 0; ks < 2; ks++) {
            int kb = ks * 16;
            unsigned a[4][4], b[2][4];
#pragma unroll
            for (int mt = 0; mt < 4; mt++) {
                int r = wm * 64 + mt * 16 + (lane & 15);
                ldsm_x4(a[mt], baseA + (unsigned)(r * 40 + kb + (lane >> 4) * 8) * 2);
            }
#pragma unroll
            for (int p = 0; p < 2; p++) {
                int kr = kb + (lane & 7) + ((lane >> 3) & 1) * 8;
                int cn = wn * 32 + p * 16 + (lane >> 4) * 8;
                ldsm_x4_t(b[p], baseB + (unsigned)(kr * 136 + cn) * 2);
            }
#pragma unroll
            for (int mt = 0; mt < 4; mt++)
#pragma unroll
                for (int p = 0; p < 2; p++) {
                    mma_f16(acc[mt][2 * p],     a[mt], &b[p][0]);
                    mma_f16(acc[mt][2 * p + 1], a[mt], &b[p][2]);
                }
        }
        __syncthreads();
    }

#pragma unroll
    for (int mt = 0; mt < 4; mt++)
#pragma unroll
        for (int nt = 0; nt < 4; nt++) {
            int r  = row0 + wm * 64 + mt * 16 + lr;
            int cl = wn * 32 + nt * 8 + lc * 2;
            int wc = wcol0 + cl;
            float b0 = bias[wc], b1 = bias[wc + 1];
            size_t o0 = (size_t)r * 512 + col0 + cl;
            size_t o1 = (size_t)(r + 8) * 512 + col0 + cl;
            *(__half2*)(g_kvh + o0) = __floats2half2_rn(acc[mt][nt][0] + b0, acc[mt][nt][1] + b1);
            *(__half2*)(g_kvh + o1) = __floats2half2_rn(acc[mt][nt][2] + b0, acc[mt][nt][3] + b1);
        }
}

// ================= unified small fp16 GEMM (3-stage ring) =================
// MODE 1: qprj g_slnh@g_whq+bq -> g_qh fp16
// MODE 2: gru  [g_updatesh|g_slotsh]@g_wgruh+g_bgru -> g_gates fp32
// MODE 3: mlp1 gelu(g_slnh@g_wh1+b1) -> g_hiddenh fp16
// MODE 4: mlp2 g_slots += g_hiddenh@g_wh2+b2 -> g_slots fp32 + g_slotsh fp16
template<int MODE>
__global__ __launch_bounds__(128) void hgemm(const float* __restrict__ bias_in) {
    constexpr int N   = (MODE == 2 || MODE == 3) ? 1024 : 256;
    constexpr int K   = (MODE == 2) ? 512 : (MODE == 4) ? 1024 : 256;
    constexpr int LDB = (MODE == 2 || MODE == 3) ? 1024 : 256;
    constexpr int LDA = (MODE == 4) ? 1024 : 256;
    constexpr int NSTAGE = K / 32;

    __shared__ __half sA[3][64 * 40];
    __shared__ __half sB[3][32 * 72];

    const __half* Abase = (MODE == 2) ? g_updatesh : (MODE == 4) ? g_hiddenh : g_slnh;
    const __half* Bh    = (MODE == 1) ? g_whq : (MODE == 2) ? g_wgruh
                        : (MODE == 3) ? g_wh1 : g_wh2;
    const float* biasp  = (MODE == 2) ? g_bgru : bias_in;

    int tid = threadIdx.x;
    int warp = tid >> 5, lane = tid & 31;
    int wm = warp & 1, wn = warp >> 1;
    int lr = lane >> 2, lc = lane & 3;
    int row0 = blockIdx.y * 64;
    int col0 = blockIdx.x * 64;

    unsigned baseA0 = smem_u32(&sA[0][0]);
    unsigned baseB0 = smem_u32(&sB[0][0]);

    auto load_stage = [&](int sidx, int bf) {
        int k0 = sidx * 32;
        const __half* Ah = Abase; int koff = k0;
        if (MODE == 2 && k0 >= 256) { Ah = g_slotsh; koff = k0 - 256; }
#pragma unroll
        for (int l = 0; l < 2; l++) {
            int task = tid + l * 128;
            int r = task >> 2, ch = task & 3;
            cp_async16(baseA0 + (unsigned)(bf * 64 * 40 + r * 40 + ch * 8) * 2,
                       Ah + (size_t)(row0 + r) * LDA + koff + ch * 8);
        }
#pragma unroll
        for (int l = 0; l < 2; l++) {
            int task = tid + l * 128;
            int r = task >> 3, ch = task & 7;
            cp_async16(baseB0 + (unsigned)(bf * 32 * 72 + r * 72 + ch * 8) * 2,
                       Bh + (size_t)(k0 + r) * LDB + col0 + ch * 8);
        }
        CP_COMMIT();
    };

    load_stage(0, 0);
    load_stage(1, 1);

    float acc[2][4][4];
#pragma unroll
    for (int mt = 0; mt < 2; mt++)
#pragma unroll
        for (int nt = 0; nt < 4; nt++)
#pragma unroll
            for (int i = 0; i < 4; i++) acc[mt][nt][i] = 0.f;

    for (int s = 0; s < NSTAGE; s++) {
        if (s + 1 < NSTAGE) CP_WAIT1(); else CP_WAIT0();
        __syncthreads();
        int bf = s % 3;
        unsigned baseA = baseA0 + (unsigned)(bf * 64 * 40) * 2;
        unsigned baseB = baseB0 + (unsigned)(bf * 32 * 72) * 2;
#pragma unroll
        for (int ks = 0; ks < 2; ks++) {
            int kb = ks * 16;
            unsigned a[2][4], b[2][4];
#pragma unroll
            for (int mt = 0; mt < 2; mt++) {
                int r = wm * 32 + mt * 16 + (lane & 15);
                ldsm_x4(a[mt], baseA + (unsigned)(r * 40 + kb + (lane >> 4) * 8) * 2);
            }
#pragma unroll
            for (int p = 0; p < 2; p++) {
                int kr = kb + (lane & 7) + ((lane >> 3) & 1) * 8;
                int cn = wn * 32 + p * 16 + (lane >> 4) * 8;
                ldsm_x4_t(b[p], baseB + (unsigned)(kr * 72 + cn) * 2);
            }
#pragma unroll
            for (int mt = 0; mt < 2; mt++)
#pragma unroll
                for (int p = 0; p < 2; p++) {
                    mma_f16(acc[mt][2 * p],     a[mt], &b[p][0]);
                    mma_f16(acc[mt][2 * p + 1], a[mt], &b[p][2]);
                }
        }
        if (s + 2 < NSTAGE) load_stage(s + 2, (s + 2) % 3);
    }

#pragma unroll
    for (int mt = 0; mt < 2; mt++)
#pragma unroll
        for (int nt = 0; nt < 4; nt++) {
            int r = row0 + wm * 32 + mt * 16 + lr;
            int c = col0 + wn * 32 + nt * 8 + lc * 2;
            float b0 = biasp[c], b1 = biasp[c + 1];
            float v0 = acc[mt][nt][0] + b0, v1 = acc[mt][nt][1] + b1;
            float v2 = acc[mt][nt][2] + b0, v3 = acc[mt][nt][3] + b1;
            if (MODE == 3) {
                v0 = 0.5f * v0 * (1.f + erff(v0 * 0.70710678118654752f));
                v1 = 0.5f * v1 * (1.f + erff(v1 * 0.70710678118654752f));
                v2 = 0.5f * v2 * (1.f + erff(v2 * 0.70710678118654752f));
                v3 = 0.5f * v3 * (1.f + erff(v3 * 0.70710678118654752f));
                *(__half2*)(g_hiddenh + (size_t)r * N + c)       = __floats2half2_rn(v0, v1);
                *(__half2*)(g_hiddenh + (size_t)(r + 8) * N + c) = __floats2half2_rn(v2, v3);
            } else if (MODE == 4) {
                v0 += g_slots[(size_t)r * N + c];       v1 += g_slots[(size_t)r * N + c + 1];
                v2 += g_slots[(size_t)(r + 8) * N + c]; v3 += g_slots[(size_t)(r + 8) * N + c + 1];
                g_slots[(size_t)r * N + c] = v0;        g_slots[(size_t)r * N + c + 1] = v1;
                g_slots[(size_t)(r + 8) * N + c] = v2;  g_slots[(size_t)(r + 8) * N + c + 1] = v3;
                *(__half2*)(g_slotsh + (size_t)r * N + c)       = __floats2half2_rn(v0, v1);
                *(__half2*)(g_slotsh + (size_t)(r + 8) * N + c) = __floats2half2_rn(v2, v3);
            } else if (MODE == 1) {
                *(__half2*)(g_qh + (size_t)r * N + c)       = __floats2half2_rn(v0, v1);
                *(__half2*)(g_qh + (size_t)(r + 8) * N + c) = __floats2half2_rn(v2, v3);
            } else {
                g_gates[(size_t)r * N + c] = v0;       g_gates[(size_t)r * N + c + 1] = v1;
                g_gates[(size_t)(r + 8) * N + c] = v2; g_gates[(size_t)(r + 8) * N + c + 1] = v3;
            }
        }
}

// ================= logits via mma + softmax =================
__global__ __launch_bounds__(128) void k_logits_mma() {
    __shared__ __half sQ[16 * 264];
    __shared__ __half sK[64 * 264];
    __shared__ float  sC[16 * 72];
    int b  = blockIdx.y;
    int n0 = blockIdx.x * 64;
    int tid = threadIdx.x;
    int warp = tid >> 5, lane = tid & 31;

    unsigned qb = smem_u32(sQ);
    unsigned kb_ = smem_u32(sK);

#pragma unroll
    for (int l = 0; l < 4; l++) {
        int task = tid + l * 128;
        int row = task >> 5, seg = task & 31;
        uint4 v = make_uint4(0, 0, 0, 0);
        if (row < 8) v = *(const uint4*)(g_qh + (size_t)(b * KS + row) * DD + seg * 8);
        *(uint4*)&sQ[row * 264 + seg * 8] = v;
    }
#pragma unroll
    for (int l = 0; l < 16; l++) {
        int task = tid + l * 128;
        int row = task >> 5, seg = task & 31;
        cp_async16(kb_ + (unsigned)(row * 264 + seg * 8) * 2,
                   g_kvh + (size_t)(b * NN + n0 + row) * 512 + seg * 8);
    }
    CP_COMMIT(); CP_WAIT0();
    __syncthreads();

    unsigned aw[16][4];
#pragma unroll
    for (int ks = 0; ks < 16; ks++)
        ldsm_x4(aw[ks], qb + (unsigned)((lane & 15) * 264 + ks * 16 + (lane >> 4) * 8) * 2);

    float acc[2][4];
#pragma unroll
    for (int f = 0; f < 2; f++)
#pragma unroll
        for (int i = 0; i < 4; i++) acc[f][i] = 0.f;

    int tokw = warp * 16;
#pragma unroll
    for (int ks = 0; ks < 16; ks++) {
        unsigned r[4];
        int nl = tokw + (lane & 7) + ((lane >> 4) & 1) * 8;
        int kh = ((lane >> 3) & 1) * 8;
        ldsm_x4(r, kb_ + (unsigned)(nl * 264 + ks * 16 + kh) * 2);
        mma_f16(acc[0], aw[ks], &r[0]);
        mma_f16(acc[1], aw[ks], &r[2]);
    }

    int lr = lane >> 2, lc = lane & 3;
#pragma unroll
    for (int f = 0; f < 2; f++) {
        int col = tokw + f * 8 + lc * 2;
        sC[lr * 72 + col]           = acc[f][0];
        sC[lr * 72 + col + 1]       = acc[f][1];
        sC[(lr + 8) * 72 + col]     = acc[f][2];
        sC[(lr + 8) * 72 + col + 1] = acc[f][3];
    }
    __syncthreads();

    if (tid < 64) {
        int tok = tid;
        float lg[8];
        float m = -1e30f;
#pragma unroll
        for (int s = 0; s < 8; s++) { lg[s] = sC[s * 72 + tok] * SCALE_QK; m = fmaxf(m, lg[s]); }
        float sum = 0.f;
#pragma unroll
        for (int s = 0; s < 8; s++) { lg[s] = expf(lg[s] - m); sum += lg[s]; }
        float inv = 1.f / sum;
#pragma unroll
        for (int s = 0; s < 8; s++) {
            float mask = lg[s] * inv;
            g_masks[((size_t)b * KS + s) * NN + n0 + tok] = mask;
            g_maskh[((size_t)b * KS + s) * NN + n0 + tok] = __float2half_rn(mask + EPSF);
            sC[s * 72 + tok] = mask;
        }
    }
    __syncthreads();
    if (tid < 8) {
        float tot = 0.f;
#pragma unroll
        for (int j = 0; j < 64; j++) tot += sC[tid * 72 + j];
        g_msum[((size_t)b * KS + tid) * 16 + blockIdx.x] = tot;
    }
}

// ================= updates via mma, N-split x2 =================
__global__ __launch_bounds__(128) void k_updates_mma() {
    __shared__ __half sAt[2][16 * 72];
    __shared__ __half sV[2][32 * 136];
    __shared__ float sden[8];
    int b = blockIdx.x;
    int colbase = blockIdx.y * 128;
    int tid = threadIdx.x;
    int warp = tid >> 5, lane = tid & 31;

    unsigned ab = smem_u32(&sAt[0][0]);
    unsigned vb = smem_u32(&sV[0][0]);

    if (tid < 8) {
        float tot = 0.f;
#pragma unroll
        for (int c = 0; c < 16; c++) tot += g_msum[((size_t)b * KS + tid) * 16 + c];
        sden[tid] = 1.f / (tot + (float)NN * EPSF + EPSF);
    }

    auto load_A = [&](int ch, int bf) {
        if (tid < 64) {
            int row = tid >> 2, seg = tid & 3;
            uint4 v = make_uint4(0, 0, 0, 0);
            if (row < 8)
                v = *(const uint4*)(g_maskh + (size_t)(b * KS + row) * NN + ch * 32 + seg * 8);
            *(uint4*)&sAt[bf][row * 72 + seg * 8] = v;
        }
    };
    auto load_V = [&](int ch, int bf) {
#pragma unroll
        for (int l = 0; l < 4; l++) {
            int task = tid + l * 128;
            int row = task >> 4, seg = task & 15;
            cp_async16(vb + (unsigned)(bf * 32 * 136 + row * 136 + seg * 8) * 2,
                       g_kvh + (size_t)(b * NN + ch * 32 + row) * 512 + 256 + colbase + seg * 8);
        }
        CP_COMMIT();
    };

    load_A(0, 0);
    load_V(0, 0);

    float acc[4][4];
#pragma unroll
    for (int g = 0; g < 4; g++)
#pragma unroll
        for (int i = 0; i < 4; i++) acc[g][i] = 0.f;

    for (int ch = 0; ch < 32; ch++) {
        if (ch < 31) { load_A(ch + 1, (ch + 1) & 1); load_V(ch + 1, (ch + 1) & 1); CP_WAIT1(); }
        else         { CP_WAIT0(); }
        __syncthreads();
        int bf = ch & 1;
        unsigned aB = ab + (unsigned)(bf * 16 * 72) * 2;
        unsigned vB = vb + (unsigned)(bf * 32 * 136) * 2;
#pragma unroll
        for (int ks = 0; ks < 2; ks++) {
            int kb = ks * 16;
            unsigned a[4];
            ldsm_x4(a, aB + (unsigned)((lane & 15) * 72 + kb + (lane >> 4) * 8) * 2);
#pragma unroll
            for (int g2 = 0; g2 < 2; g2++) {
                unsigned bfrag[4];
                int kr = kb + (lane & 7) + ((lane >> 3) & 1) * 8;
                int cn = warp * 32 + g2 * 16 + (lane >> 4) * 8;
                ldsm_x4_t(bfrag, vB + (unsigned)(kr * 136 + cn) * 2);
                mma_f16(acc[g2 * 2],     a, &bfrag[0]);
                mma_f16(acc[g2 * 2 + 1], a, &bfrag[2]);
            }
        }
        __syncthreads();
    }

    int lr = lane >> 2, lc = lane & 3;
    float inv = sden[lr];
#pragma unroll
    for (int g = 0; g < 4; g++) {
        int col = colbase + warp * 32 + (g >> 1) * 16 + (g & 1) * 8 + lc * 2;
        *(__half2*)(g_updatesh + (size_t)(b * KS + lr) * DD + col) =
            __floats2half2_rn(acc[g][0] * inv, acc[g][1] * inv);
    }
}

// ---------------- LN of slots -> g_slnh ----------------
__global__ __launch_bounds__(256) void k_ln_slots(const float* __restrict__ g,
                                                  const float* __restrict__ b) {
    int row = blockIdx.x, c = threadIdx.x;
    float x = g_slots[row * DD + c];
    float s1 = x, s2 = x * x;
#pragma unroll
    for (int o = 16; o; o >>= 1) {
        s1 += __shfl_xor_sync(0xFFFFFFFFu, s1, o);
        s2 += __shfl_xor_sync(0xFFFFFFFFu, s2, o);
    }
    __shared__ float r1[8], r2[8];
    if ((c & 31) == 0) { r1[c >> 5] = s1; r2[c >> 5] = s2; }
    __syncthreads();
    float t1 = 0.f, t2 = 0.f;
#pragma unroll
    for (int w = 0; w < 8; w++) { t1 += r1[w]; t2 += r2[w]; }
    float mean = t1 * (1.f / DD);
    float inv  = rsqrtf(t2 * (1.f / DD) - mean * mean + LN_EPS);
    g_slnh[row * DD + c] = __float2half_rn((x - mean) * inv * g[c] + b[c]);
}

// ---------------- GRU gating + LN(slots) for MLP ----------------
__global__ __launch_bounds__(256) void k_gru_combine_ln(const float* __restrict__ lg,
                                                        const float* __restrict__ lb) {
    int row = blockIdx.x, c = threadIdx.x;
    const float* gt = g_gates + (size_t)row * 1024;
    float sp = g_slots[row * DD + c];
    float r = 1.f / (1.f + expf(-gt[c]));
    float z = 1.f / (1.f + expf(-gt[256 + c]));
    float n = tanhf(gt[512 + c] + r * gt[768 + c]);
    float sN = (1.f - z) * n + z * sp;
    g_slots[row * DD + c] = sN;
    float s1 = sN, s2 = sN * sN;
#pragma unroll
    for (int o = 16; o; o >>= 1) {
        s1 += __shfl_xor_sync(0xFFFFFFFFu, s1, o);
        s2 += __shfl_xor_sync(0xFFFFFFFFu, s2, o);
    }
    __shared__ float r1[8], r2[8];
    if ((c & 31) == 0) { r1[c >> 5] = s1; r2[c >> 5] = s2; }
    __syncthreads();
    float t1 = 0.f, t2 = 0.f;
#pragma unroll
    for (int w = 0; w < 8; w++) { t1 += r1[w]; t2 += r2[w]; }
    float mean = t1 * (1.f / DD);
    float inv  = rsqrtf(t2 * (1.f / DD) - mean * mean + LN_EPS);
    g_slnh[row * DD + c] = __float2half_rn((sN - mean) * inv * lg[c] + lb[c]);
}

// ---------------- pack output ----------------
__global__ void k_out(float* __restrict__ out, int total) {
    for (int idx = blockIdx.x * blockDim.x + threadIdx.x; idx < total;
         idx += gridDim.x * blockDim.x) {
        out[idx] = (idx < BB * KS * DD) ? g_slots[idx] : g_masks[idx - BB * KS * DD];
    }
}

// ---------------- launch ----------------
extern "C" void kernel_launch(void* const* d_in, const int* in_sizes, int n_in,
                              void* d_out, int out_size) {
    const float* tokens     = (const float*)d_in[0];
    const float* init_slots = (const float*)d_in[1];
    const float* ln_in_g    = (const float*)d_in[2];
    const float* ln_in_b    = (const float*)d_in[3];
    const float* Wk         = (const float*)d_in[4];
    const float* bk         = (const float*)d_in[5];
    const float* Wv         = (const float*)d_in[6];
    const float* bv         = (const float*)d_in[7];
    const float* ln_s_g     = (const float*)d_in[8];
    const float* ln_s_b     = (const float*)d_in[9];
    const float* Wq         = (const float*)d_in[10];
    const float* bq         = (const float*)d_in[11];
    const float* W_ih       = (const float*)d_in[12];
    const float* b_ih       = (const float*)d_in[13];
    const float* W_hh       = (const float*)d_in[14];
    const float* b_hh       = (const float*)d_in[15];
    const float* ln_m_g     = (const float*)d_in[16];
    const float* ln_m_b     = (const float*)d_in[17];
    const float* W1         = (const float*)d_in[18];
    const float* b1         = (const float*)d_in[19];
    const float* W2         = (const float*)d_in[20];
    const float* b2         = (const float*)d_in[21];

    k_prep_all<<<4872, 256>>>(init_slots, Wk, Wv, W_ih, W_hh, b_ih, b_hh, Wq, W1, W2);
    k_ln_apply<<<BB * NN / 8, 256>>>(tokens, ln_in_g, ln_in_b);
    k_gemm_kv_a<<<dim3(4, 1024), 256>>>(bk, bv);

    for (int it = 0; it < 3; it++) {
        k_ln_slots<<<BB * KS, 256>>>(ln_s_g, ln_s_b);
        hgemm<1><<<dim3(4, 16), 128>>>(bq);
        k_logits_mma<<<dim3(16, BB), 128>>>();
        k_updates_mma<<<dim3(BB, 2), 128>>>();
        hgemm<2><<<dim3(16, 16), 128>>>(nullptr);
        k_gru_combine_ln<<<BB * KS, 256>>>(ln_m_g, ln_m_b);
        hgemm<3><<<dim3(16, 16), 128>>>(b1);
        hgemm<4><<<dim3(4, 16), 128>>>(b2);
    }

    k_out<<<2560, 256>>>((float*)d_out, out_size);
}